// round 1
// baseline (speedup 1.0000x reference)
#include <cuda_runtime.h>
#include <math.h>

#define NN   100000
#define EE   3200000
#define INC  128
#define HIDC 16

// ---------------- scratch (no allocations allowed) ----------------
__device__ float g_deg[NN];
__device__ float g_dinv[NN];
__device__ float g_h1[(long long)NN * HIDC];
__device__ float g_agg1[(long long)NN * HIDC];
__device__ float g_h2[NN];
__device__ float g_agg2[NN];
__device__ int   g_is64;

// ---------------- edge index dtype auto-detect --------------------
// If the buffer is int32, reading it as int64 packs two indices:
// v = lo + hi*2^32 with hi in [0,N) -> almost surely out of range.
__global__ void detect_kernel(const void* ei) {
    __shared__ int bad;
    if (threadIdx.x == 0) bad = 0;
    __syncthreads();
    const long long* p = (const long long*)ei;
    long long v = p[threadIdx.x];          // first 256 int64 slots (2KB, in bounds either way)
    if (v < 0 || v >= NN) bad = 1;
    __syncthreads();
    if (threadIdx.x == 0) g_is64 = bad ? 0 : 1;
}

__device__ __forceinline__ void load_edge(const void* ei, int is64, long long e,
                                          int& s, int& d) {
    if (is64) {
        const long long* p = (const long long*)ei;
        s = (int)p[e];
        d = (int)p[(long long)EE + e];
    } else {
        const int* p = (const int*)ei;
        s = p[e];
        d = p[(long long)EE + e];
    }
}

// ---------------- degree ----------------
__global__ void degree_kernel(const void* ei) {
    long long e = (long long)blockIdx.x * blockDim.x + threadIdx.x;
    if (e >= EE) return;
    int is64 = g_is64;
    int s, d;
    load_edge(ei, is64, e, s, d);
    atomicAdd(&g_deg[d], 1.0f);
}

__global__ void dinv_kernel() {
    int i = blockIdx.x * blockDim.x + threadIdx.x;
    if (i >= NN) return;
    float deg = g_deg[i] + 1.0f;           // self-loop
    g_dinv[i] = rsqrtf(deg);               // deg >= 1 always
}

// ---------------- h1 = x @ W1 (smem-tiled, 16 nodes/block) ----------------
__global__ void gemm1_kernel(const float* __restrict__ x, const float* __restrict__ W1) {
    __shared__ float sW[INC * HIDC];       // 8KB
    __shared__ float sx[16 * INC];         // 8KB
    int t = threadIdx.x;                   // 256 threads
    for (int i = t; i < INC * HIDC; i += 256) sW[i] = W1[i];
    long long base = (long long)blockIdx.x * 16;
    for (int i = t; i < 16 * INC; i += 256) {
        long long node = base + i / INC;
        sx[i] = (node < NN) ? x[node * INC + (i % INC)] : 0.0f;
    }
    __syncthreads();
    int local = t / HIDC;                  // 0..15
    int c     = t % HIDC;
    long long node = base + local;
    float acc = 0.0f;
#pragma unroll 8
    for (int k = 0; k < INC; k++) acc = fmaf(sx[local * INC + k], sW[k * HIDC + c], acc);
    if (node < NN) g_h1[node * HIDC + c] = acc;
}

// ---------------- layer-1 aggregation: 16 lanes per edge ----------------
__global__ void agg1_kernel(const void* ei) {
    long long g = (long long)blockIdx.x * blockDim.x + threadIdx.x;
    if (g >= (long long)EE * HIDC) return;
    long long e = g >> 4;
    int c = (int)(g & 15);
    int is64 = g_is64;
    int s, d;
    load_edge(ei, is64, e, s, d);
    float norm = g_dinv[s] * g_dinv[d];
    float v = g_h1[(long long)s * HIDC + c] * norm;
    atomicAdd(&g_agg1[(long long)d * HIDC + c], v);
}

// ---------------- self-loop + bias + relu + (16->1) GEMM fused ----------------
__global__ void post1_kernel(const float* __restrict__ b1, const float* __restrict__ W2) {
    long long g = (long long)blockIdx.x * blockDim.x + threadIdx.x;
    long long node = g >> 4;
    int c = (int)(g & 15);
    if (node >= NN) return;
    float di = g_dinv[node];
    float v = g_agg1[node * HIDC + c] + g_h1[node * HIDC + c] * di * di + b1[c];
    v = fmaxf(v, 0.0f);
    v *= W2[c];
    // reduce 16 lanes -> h2
#pragma unroll
    for (int off = 8; off; off >>= 1)
        v += __shfl_down_sync(0xffffffffu, v, off, 16);
    if (c == 0) g_h2[node] = v;
}

// ---------------- layer-2 aggregation: 1 atomic per edge ----------------
__global__ void agg2_kernel(const void* ei) {
    long long e = (long long)blockIdx.x * blockDim.x + threadIdx.x;
    if (e >= EE) return;
    int is64 = g_is64;
    int s, d;
    load_edge(ei, is64, e, s, d);
    float norm = g_dinv[s] * g_dinv[d];
    atomicAdd(&g_agg2[d], g_h2[s] * norm);
}

// ---------------- final: self-loop + bias + sigmoid ----------------
__global__ void final_kernel(const float* __restrict__ b2, float* __restrict__ out) {
    int i = blockIdx.x * blockDim.x + threadIdx.x;
    if (i >= NN) return;
    float di = g_dinv[i];
    float v = g_agg2[i] + g_h2[i] * di * di + b2[0];
    out[i] = 1.0f / (1.0f + expf(-v));
}

extern "C" void kernel_launch(void* const* d_in, const int* in_sizes, int n_in,
                              void* d_out, int out_size) {
    const float* x  = (const float*)d_in[0];
    const void*  ei = d_in[1];
    const float* W1 = (const float*)d_in[2];
    const float* b1 = (const float*)d_in[3];
    const float* W2 = (const float*)d_in[4];
    const float* b2 = (const float*)d_in[5];
    float* out = (float*)d_out;

    // zero the per-call accumulators (graph-capturable memset nodes)
    void *p_deg, *p_agg1, *p_agg2;
    cudaGetSymbolAddress(&p_deg,  g_deg);
    cudaGetSymbolAddress(&p_agg1, g_agg1);
    cudaGetSymbolAddress(&p_agg2, g_agg2);
    cudaMemsetAsync(p_deg,  0, (size_t)NN * sizeof(float));
    cudaMemsetAsync(p_agg1, 0, (size_t)NN * HIDC * sizeof(float));
    cudaMemsetAsync(p_agg2, 0, (size_t)NN * sizeof(float));

    detect_kernel<<<1, 256>>>(ei);

    degree_kernel<<<(EE + 255) / 256, 256>>>(ei);
    dinv_kernel<<<(NN + 255) / 256, 256>>>();

    gemm1_kernel<<<(NN + 15) / 16, 256>>>(x, W1);

    long long t1 = (long long)EE * HIDC;
    agg1_kernel<<<(unsigned)((t1 + 255) / 256), 256>>>(ei);

    long long t2 = (long long)NN * HIDC;
    post1_kernel<<<(unsigned)((t2 + 255) / 256), 256>>>(b1, W2);

    agg2_kernel<<<(EE + 255) / 256, 256>>>(ei);

    final_kernel<<<(NN + 255) / 256, 256>>>(b2, out);
}

// round 2
// speedup vs baseline: 1.1448x; 1.1448x over previous
#include <cuda_runtime.h>
#include <math.h>

#define NN   100000
#define EE   3200000
#define INC  128
#define HIDC 16

// ---------------- scratch (no allocations allowed) ----------------
__device__ float g_deg[NN];
__device__ float g_dinv[NN];
__device__ float g_h1[(long long)NN * HIDC];
__device__ float g_agg1[(long long)NN * HIDC];
__device__ float g_h2[NN];
__device__ float g_agg2[NN];
__device__ int   g_is64;

// ---------------- edge index dtype auto-detect --------------------
__global__ void detect_kernel(const void* ei) {
    __shared__ int bad;
    if (threadIdx.x == 0) bad = 0;
    __syncthreads();
    const long long* p = (const long long*)ei;
    long long v = p[threadIdx.x];
    if (v < 0 || v >= NN) bad = 1;
    __syncthreads();
    if (threadIdx.x == 0) g_is64 = bad ? 0 : 1;
}

__device__ __forceinline__ void load_edge(const void* ei, int is64, long long e,
                                          int& s, int& d) {
    if (is64) {
        const long long* p = (const long long*)ei;
        s = (int)p[e];
        d = (int)p[(long long)EE + e];
    } else {
        const int* p = (const int*)ei;
        s = p[e];
        d = p[(long long)EE + e];
    }
}

__device__ __forceinline__ void red_add_v4(float* gp, float a, float b, float c, float d) {
    asm volatile("red.global.add.v4.f32 [%0], {%1,%2,%3,%4};"
        :: "l"(__cvta_generic_to_global(gp)), "f"(a), "f"(b), "f"(c), "f"(d)
        : "memory");
}

// ---------------- degree ----------------
__global__ void degree_kernel(const void* ei) {
    long long e = (long long)blockIdx.x * blockDim.x + threadIdx.x;
    if (e >= EE) return;
    int is64 = g_is64;
    int d;
    if (is64) {
        const long long* p = (const long long*)ei;
        d = (int)p[(long long)EE + e];
    } else {
        const int* p = (const int*)ei;
        d = p[(long long)EE + e];
    }
    atomicAdd(&g_deg[d], 1.0f);
}

__global__ void dinv_kernel() {
    int i = blockIdx.x * blockDim.x + threadIdx.x;
    if (i >= NN) return;
    float deg = g_deg[i] + 1.0f;           // self-loop
    g_dinv[i] = rsqrtf(deg);
}

// ---------------- h1 = x @ W1 ----------------
// 128 threads/block, one node per thread, 16 channel accumulators in regs.
// W reads are warp-uniform (LDS broadcast); x reads conflict-free (stride 65).
__global__ void gemm1_kernel(const float* __restrict__ x, const float* __restrict__ W1) {
    __shared__ float sW[INC * HIDC];     // 8KB
    __shared__ float sx[128 * 65];       // 33.3KB, padded rows
    int t = threadIdx.x;                 // 128 threads
    long long base = (long long)blockIdx.x * 128;

    for (int i = t; i < INC * HIDC; i += 128) sW[i] = W1[i];

    float acc[HIDC];
#pragma unroll
    for (int c = 0; c < HIDC; c++) acc[c] = 0.0f;

    for (int kt = 0; kt < 2; kt++) {
        __syncthreads();
        for (int i = t; i < 128 * 64; i += 128) {
            int r = i >> 6, c = i & 63;
            long long node = base + r;
            sx[r * 65 + c] = (node < NN) ? x[node * INC + kt * 64 + c] : 0.0f;
        }
        __syncthreads();
        const float* xr = &sx[t * 65];
        const float* wb = &sW[kt * 64 * HIDC];
#pragma unroll 8
        for (int k = 0; k < 64; k++) {
            float xv = xr[k];
            const float4* wr = (const float4*)(wb + k * HIDC);
            float4 w0 = wr[0], w1 = wr[1], w2 = wr[2], w3 = wr[3];
            acc[0]  = fmaf(xv, w0.x, acc[0]);  acc[1]  = fmaf(xv, w0.y, acc[1]);
            acc[2]  = fmaf(xv, w0.z, acc[2]);  acc[3]  = fmaf(xv, w0.w, acc[3]);
            acc[4]  = fmaf(xv, w1.x, acc[4]);  acc[5]  = fmaf(xv, w1.y, acc[5]);
            acc[6]  = fmaf(xv, w1.z, acc[6]);  acc[7]  = fmaf(xv, w1.w, acc[7]);
            acc[8]  = fmaf(xv, w2.x, acc[8]);  acc[9]  = fmaf(xv, w2.y, acc[9]);
            acc[10] = fmaf(xv, w2.z, acc[10]); acc[11] = fmaf(xv, w2.w, acc[11]);
            acc[12] = fmaf(xv, w3.x, acc[12]); acc[13] = fmaf(xv, w3.y, acc[13]);
            acc[14] = fmaf(xv, w3.z, acc[14]); acc[15] = fmaf(xv, w3.w, acc[15]);
        }
    }
    long long node = base + t;
    if (node < NN) {
        float4* o = (float4*)&g_h1[node * HIDC];
        o[0] = make_float4(acc[0],  acc[1],  acc[2],  acc[3]);
        o[1] = make_float4(acc[4],  acc[5],  acc[6],  acc[7]);
        o[2] = make_float4(acc[8],  acc[9],  acc[10], acc[11]);
        o[3] = make_float4(acc[12], acc[13], acc[14], acc[15]);
    }
}

// ---------------- layer-1 aggregation: 1 thread/edge, vector RED ----------------
__global__ void agg1_kernel(const void* ei) {
    long long e = (long long)blockIdx.x * blockDim.x + threadIdx.x;
    if (e >= EE) return;
    int is64 = g_is64;
    int s, d;
    load_edge(ei, is64, e, s, d);
    float norm = g_dinv[s] * g_dinv[d];
    const float4* hp = (const float4*)&g_h1[(long long)s * HIDC];
    float4 h0 = hp[0], h1 = hp[1], h2 = hp[2], h3 = hp[3];
    float* op = &g_agg1[(long long)d * HIDC];
    red_add_v4(op +  0, h0.x*norm, h0.y*norm, h0.z*norm, h0.w*norm);
    red_add_v4(op +  4, h1.x*norm, h1.y*norm, h1.z*norm, h1.w*norm);
    red_add_v4(op +  8, h2.x*norm, h2.y*norm, h2.z*norm, h2.w*norm);
    red_add_v4(op + 12, h3.x*norm, h3.y*norm, h3.z*norm, h3.w*norm);
}

// ---------------- self-loop + bias + relu + (16->1) GEMM fused ----------------
__global__ void post1_kernel(const float* __restrict__ b1, const float* __restrict__ W2) {
    long long g = (long long)blockIdx.x * blockDim.x + threadIdx.x;
    long long node = g >> 4;
    int c = (int)(g & 15);
    if (node >= NN) return;
    float di = g_dinv[node];
    float v = g_agg1[node * HIDC + c] + g_h1[node * HIDC + c] * di * di + b1[c];
    v = fmaxf(v, 0.0f);
    v *= W2[c];
#pragma unroll
    for (int off = 8; off; off >>= 1)
        v += __shfl_down_sync(0xffffffffu, v, off, 16);
    if (c == 0) g_h2[node] = v;
}

// ---------------- layer-2 aggregation ----------------
__global__ void agg2_kernel(const void* ei) {
    long long e = (long long)blockIdx.x * blockDim.x + threadIdx.x;
    if (e >= EE) return;
    int is64 = g_is64;
    int s, d;
    load_edge(ei, is64, e, s, d);
    float norm = g_dinv[s] * g_dinv[d];
    atomicAdd(&g_agg2[d], g_h2[s] * norm);
}

// ---------------- final: self-loop + bias + sigmoid ----------------
__global__ void final_kernel(const float* __restrict__ b2, float* __restrict__ out) {
    int i = blockIdx.x * blockDim.x + threadIdx.x;
    if (i >= NN) return;
    float di = g_dinv[i];
    float v = g_agg2[i] + g_h2[i] * di * di + b2[0];
    out[i] = 1.0f / (1.0f + expf(-v));
}

extern "C" void kernel_launch(void* const* d_in, const int* in_sizes, int n_in,
                              void* d_out, int out_size) {
    const float* x  = (const float*)d_in[0];
    const void*  ei = d_in[1];
    const float* W1 = (const float*)d_in[2];
    const float* b1 = (const float*)d_in[3];
    const float* W2 = (const float*)d_in[4];
    const float* b2 = (const float*)d_in[5];
    float* out = (float*)d_out;

    void *p_deg, *p_agg1, *p_agg2;
    cudaGetSymbolAddress(&p_deg,  g_deg);
    cudaGetSymbolAddress(&p_agg1, g_agg1);
    cudaGetSymbolAddress(&p_agg2, g_agg2);
    cudaMemsetAsync(p_deg,  0, (size_t)NN * sizeof(float));
    cudaMemsetAsync(p_agg1, 0, (size_t)NN * HIDC * sizeof(float));
    cudaMemsetAsync(p_agg2, 0, (size_t)NN * sizeof(float));

    detect_kernel<<<1, 256>>>(ei);

    degree_kernel<<<(EE + 255) / 256, 256>>>(ei);
    dinv_kernel<<<(NN + 255) / 256, 256>>>();

    gemm1_kernel<<<(NN + 127) / 128, 128>>>(x, W1);

    agg1_kernel<<<(EE + 255) / 256, 256>>>(ei);

    long long t2 = (long long)NN * HIDC;
    post1_kernel<<<(unsigned)((t2 + 255) / 256), 256>>>(b1, W2);

    agg2_kernel<<<(EE + 255) / 256, 256>>>(ei);

    final_kernel<<<(NN + 255) / 256, 256>>>(b2, out);
}

// round 3
// speedup vs baseline: 1.2577x; 1.0986x over previous
#include <cuda_runtime.h>
#include <math.h>

#define NN   100000
#define EE   3200000
#define INC  128
#define HIDC 16

// ---------------- scratch ----------------
__device__ float g_deg[NN];
__device__ float g_dinv[NN];
__device__ float g_h1[(long long)NN * HIDC];
__device__ float g_agg1[(long long)NN * HIDC];
__device__ float g_h2[NN];
__device__ float g_agg2[NN];
__device__ int   g_is64;
__device__ int2  g_sd[EE];     // packed (src,dst)
__device__ float g_norm[EE];   // precomputed dinv[s]*dinv[d]

// ---------------- edge index dtype auto-detect --------------------
__global__ void detect_kernel(const void* ei) {
    __shared__ int bad;
    if (threadIdx.x == 0) bad = 0;
    __syncthreads();
    const long long* p = (const long long*)ei;
    long long v = p[threadIdx.x];
    if (v < 0 || v >= NN) bad = 1;
    __syncthreads();
    if (threadIdx.x == 0) g_is64 = bad ? 0 : 1;
}

// ---------------- degree ----------------
__global__ void degree_kernel(const void* ei) {
    long long e = (long long)blockIdx.x * blockDim.x + threadIdx.x;
    if (e >= EE) return;
    int d;
    if (g_is64) {
        const long long* p = (const long long*)ei;
        d = (int)p[(long long)EE + e];
    } else {
        const int* p = (const int*)ei;
        d = p[(long long)EE + e];
    }
    atomicAdd(&g_deg[d], 1.0f);
}

__global__ void dinv_kernel() {
    int i = blockIdx.x * blockDim.x + threadIdx.x;
    if (i >= NN) return;
    g_dinv[i] = rsqrtf(g_deg[i] + 1.0f);
}

// ---------------- pack edges: (s,d) int2 + norm ----------------
__global__ void pack_kernel(const void* ei) {
    long long e = (long long)blockIdx.x * blockDim.x + threadIdx.x;
    if (e >= EE) return;
    int s, d;
    if (g_is64) {
        const long long* p = (const long long*)ei;
        s = (int)p[e];
        d = (int)p[(long long)EE + e];
    } else {
        const int* p = (const int*)ei;
        s = p[e];
        d = p[(long long)EE + e];
    }
    g_sd[e] = make_int2(s, d);
    g_norm[e] = g_dinv[s] * g_dinv[d];
}

// ---------------- h1 = x @ W1 ----------------
// 256 threads = 64 nodes x 4 threads; each thread computes 4 channels.
// K tiled 2x64. sx padded stride 68 (68%32==4 -> 8 locals hit distinct banks).
__global__ void __launch_bounds__(256) gemm1_kernel(const float* __restrict__ x,
                                                    const float* __restrict__ W1) {
    __shared__ float sW[INC * HIDC];     // 8KB
    __shared__ float sx[64 * 68];        // 17.4KB
    int t = threadIdx.x;
    long long base = (long long)blockIdx.x * 64;
    int local = t >> 2;                  // 0..63 node within block
    int cg    = (t & 3) * 4;             // channel group start

    for (int i = t; i < INC * HIDC; i += 256) sW[i] = W1[i];

    float a0 = 0.f, a1 = 0.f, a2 = 0.f, a3 = 0.f;

#pragma unroll
    for (int kt = 0; kt < 2; kt++) {
        __syncthreads();
        // stage 64 nodes x 64 k-values, coalesced float4 global loads
        {
            const float4* x4 = (const float4*)x;
            // 64*64 floats = 1024 float4; thread t loads 4 of them
            for (int j = t; j < 1024; j += 256) {
                int r  = j >> 4;         // node local (16 float4 per 64-col row)
                int c4 = j & 15;
                long long node = base + r;
                float4 v = (node < NN) ? x4[node * 32 + kt * 16 + c4]
                                       : make_float4(0.f, 0.f, 0.f, 0.f);
                *(float4*)&sx[r * 68 + c4 * 4] = v;
            }
        }
        __syncthreads();
        const float* xr = &sx[local * 68];
        const float* wb = &sW[kt * 64 * HIDC + cg];
#pragma unroll 8
        for (int k = 0; k < 64; k++) {
            float xv = xr[k];
            float4 w = *(const float4*)(wb + k * HIDC);
            a0 = fmaf(xv, w.x, a0);
            a1 = fmaf(xv, w.y, a1);
            a2 = fmaf(xv, w.z, a2);
            a3 = fmaf(xv, w.w, a3);
        }
    }
    long long node = base + local;
    if (node < NN)
        *(float4*)&g_h1[node * HIDC + cg] = make_float4(a0, a1, a2, a3);
}

__device__ __forceinline__ void red_add_v4(float* gp, float a, float b, float c, float d) {
    asm volatile("red.global.add.v4.f32 [%0], {%1,%2,%3,%4};"
        :: "l"(__cvta_generic_to_global(gp)), "f"(a), "f"(b), "f"(c), "f"(d)
        : "memory");
}

// ---------------- layer-1 aggregation ----------------
__global__ void agg1_kernel() {
    long long e = (long long)blockIdx.x * blockDim.x + threadIdx.x;
    if (e >= EE) return;
    int2 sd = g_sd[e];
    float norm = g_norm[e];
    const float4* hp = (const float4*)&g_h1[(long long)sd.x * HIDC];
    float4 h0 = hp[0], h1 = hp[1], h2 = hp[2], h3 = hp[3];
    float* op = &g_agg1[(long long)sd.y * HIDC];
    red_add_v4(op +  0, h0.x*norm, h0.y*norm, h0.z*norm, h0.w*norm);
    red_add_v4(op +  4, h1.x*norm, h1.y*norm, h1.z*norm, h1.w*norm);
    red_add_v4(op +  8, h2.x*norm, h2.y*norm, h2.z*norm, h2.w*norm);
    red_add_v4(op + 12, h3.x*norm, h3.y*norm, h3.z*norm, h3.w*norm);
}

// ---------------- self-loop + bias + relu + (16->1) GEMM fused ----------------
__global__ void post1_kernel(const float* __restrict__ b1, const float* __restrict__ W2) {
    long long g = (long long)blockIdx.x * blockDim.x + threadIdx.x;
    long long node = g >> 4;
    int c = (int)(g & 15);
    if (node >= NN) return;
    float di = g_dinv[node];
    float v = g_agg1[node * HIDC + c] + g_h1[node * HIDC + c] * di * di + b1[c];
    v = fmaxf(v, 0.0f);
    v *= W2[c];
#pragma unroll
    for (int off = 8; off; off >>= 1)
        v += __shfl_down_sync(0xffffffffu, v, off, 16);
    if (c == 0) g_h2[node] = v;
}

// ---------------- layer-2 aggregation ----------------
__global__ void agg2_kernel() {
    long long e = (long long)blockIdx.x * blockDim.x + threadIdx.x;
    if (e >= EE) return;
    int2 sd = g_sd[e];
    float v = g_h2[sd.x] * g_norm[e];
    asm volatile("red.global.add.f32 [%0], %1;"
        :: "l"(__cvta_generic_to_global(&g_agg2[sd.y])), "f"(v) : "memory");
}

// ---------------- final ----------------
__global__ void final_kernel(const float* __restrict__ b2, float* __restrict__ out) {
    int i = blockIdx.x * blockDim.x + threadIdx.x;
    if (i >= NN) return;
    float di = g_dinv[i];
    float v = g_agg2[i] + g_h2[i] * di * di + b2[0];
    out[i] = 1.0f / (1.0f + expf(-v));
}

extern "C" void kernel_launch(void* const* d_in, const int* in_sizes, int n_in,
                              void* d_out, int out_size) {
    const float* x  = (const float*)d_in[0];
    const void*  ei = d_in[1];
    const float* W1 = (const float*)d_in[2];
    const float* b1 = (const float*)d_in[3];
    const float* W2 = (const float*)d_in[4];
    const float* b2 = (const float*)d_in[5];
    float* out = (float*)d_out;

    void *p_deg, *p_agg1, *p_agg2;
    cudaGetSymbolAddress(&p_deg,  g_deg);
    cudaGetSymbolAddress(&p_agg1, g_agg1);
    cudaGetSymbolAddress(&p_agg2, g_agg2);
    cudaMemsetAsync(p_deg,  0, (size_t)NN * sizeof(float));
    cudaMemsetAsync(p_agg1, 0, (size_t)NN * HIDC * sizeof(float));
    cudaMemsetAsync(p_agg2, 0, (size_t)NN * sizeof(float));

    detect_kernel<<<1, 256>>>(ei);
    degree_kernel<<<(EE + 255) / 256, 256>>>(ei);
    dinv_kernel<<<(NN + 255) / 256, 256>>>();
    pack_kernel<<<(EE + 255) / 256, 256>>>(ei);

    gemm1_kernel<<<(NN + 63) / 64, 256>>>(x, W1);

    agg1_kernel<<<(EE + 255) / 256, 256>>>();

    long long t2 = (long long)NN * HIDC;
    post1_kernel<<<(unsigned)((t2 + 255) / 256), 256>>>(b1, W2);

    agg2_kernel<<<(EE + 255) / 256, 256>>>();

    final_kernel<<<(NN + 255) / 256, 256>>>(b2, out);
}

// round 4
// speedup vs baseline: 1.5674x; 1.2462x over previous
#include <cuda_runtime.h>
#include <math.h>

#define NN   100000
#define EE   3200000
#define INC  128
#define HIDC 16
#define SCAN_B 1024
#define NBLK ((NN + SCAN_B - 1) / SCAN_B)   // 98

// ---------------- scratch ----------------
__device__ int   g_degi[NN];
__device__ float g_dinv[NN];
__device__ int2  g_sd[EE];
__device__ int   g_start[NN + 1];
__device__ int   g_cur[NN];
__device__ int   g_bsum[128];
__device__ int2  g_csr[EE];               // (src, norm bits)
__device__ float g_h1[(long long)NN * HIDC];
__device__ float g_h2[NN];
__device__ int   g_is64;

// ---------------- edge dtype auto-detect ----------------
__global__ void detect_kernel(const void* ei) {
    __shared__ int bad;
    if (threadIdx.x == 0) bad = 0;
    __syncthreads();
    const long long* p = (const long long*)ei;
    long long v = p[threadIdx.x];
    if (v < 0 || v >= NN) bad = 1;
    __syncthreads();
    if (threadIdx.x == 0) g_is64 = bad ? 0 : 1;
}

// ---------------- degree + pack (one pass over edge index) ----------------
__global__ void degree_pack_kernel(const void* ei) {
    long long e = (long long)blockIdx.x * blockDim.x + threadIdx.x;
    if (e >= EE) return;
    int s, d;
    if (g_is64) {
        const long long* p = (const long long*)ei;
        s = (int)p[e];
        d = (int)p[(long long)EE + e];
    } else {
        const int* p = (const int*)ei;
        s = p[e];
        d = p[(long long)EE + e];
    }
    g_sd[e] = make_int2(s, d);
    atomicAdd(&g_degi[d], 1);
}

__global__ void dinv_kernel() {
    int i = blockIdx.x * blockDim.x + threadIdx.x;
    if (i >= NN) return;
    g_dinv[i] = rsqrtf((float)g_degi[i] + 1.0f);
}

// ---------------- prefix scan (3 kernels) ----------------
__global__ void scan1_kernel() {
    __shared__ int sh[SCAN_B];
    int t = threadIdx.x;
    int i = blockIdx.x * SCAN_B + t;
    int v = (i < NN) ? g_degi[i] : 0;
    sh[t] = v;
#pragma unroll
    for (int off = 1; off < SCAN_B; off <<= 1) {
        __syncthreads();
        int add = (t >= off) ? sh[t - off] : 0;
        __syncthreads();
        sh[t] += add;
    }
    __syncthreads();
    if (i < NN) g_start[i] = sh[t] - v;          // exclusive within block
    if (t == SCAN_B - 1) g_bsum[blockIdx.x] = sh[t];
}

__global__ void scan2_kernel() {
    __shared__ int sh[128];
    int t = threadIdx.x;                          // 128 threads
    int v = (t < NBLK) ? g_bsum[t] : 0;
    sh[t] = v;
#pragma unroll
    for (int off = 1; off < 128; off <<= 1) {
        __syncthreads();
        int add = (t >= off) ? sh[t - off] : 0;
        __syncthreads();
        sh[t] += add;
    }
    __syncthreads();
    if (t < NBLK) g_bsum[t] = sh[t] - v;          // exclusive
}

__global__ void scan3_kernel() {
    int i = blockIdx.x * blockDim.x + threadIdx.x;
    if (i >= NN) return;
    int s = g_start[i] + g_bsum[i >> 10];
    g_start[i] = s;
    g_cur[i] = s;
    if (i == 0) g_start[NN] = EE;
}

// ---------------- scatter edges into CSR ----------------
__global__ void scatter_kernel() {
    long long e = (long long)blockIdx.x * blockDim.x + threadIdx.x;
    if (e >= EE) return;
    int2 sd = g_sd[e];
    float norm = g_dinv[sd.x] * g_dinv[sd.y];
    int pos = atomicAdd(&g_cur[sd.y], 1);
    g_csr[pos] = make_int2(sd.x, __float_as_int(norm));
}

// ---------------- h1 = x @ W1 ----------------
__global__ void __launch_bounds__(256) gemm1_kernel(const float* __restrict__ x,
                                                    const float* __restrict__ W1) {
    __shared__ float sW[INC * HIDC];
    __shared__ float sx[64 * 68];
    int t = threadIdx.x;
    long long base = (long long)blockIdx.x * 64;
    int local = t >> 2;
    int cg    = (t & 3) * 4;

    for (int i = t; i < INC * HIDC; i += 256) sW[i] = W1[i];

    float a0 = 0.f, a1 = 0.f, a2 = 0.f, a3 = 0.f;

#pragma unroll
    for (int kt = 0; kt < 2; kt++) {
        __syncthreads();
        const float4* x4 = (const float4*)x;
        for (int j = t; j < 1024; j += 256) {
            int r = j >> 4, c4 = j & 15;
            long long node = base + r;
            float4 v = (node < NN) ? x4[node * 32 + kt * 16 + c4]
                                   : make_float4(0.f, 0.f, 0.f, 0.f);
            *(float4*)&sx[r * 68 + c4 * 4] = v;
        }
        __syncthreads();
        const float* xr = &sx[local * 68];
        const float* wb = &sW[kt * 64 * HIDC + cg];
#pragma unroll 8
        for (int k = 0; k < 64; k++) {
            float xv = xr[k];
            float4 w = *(const float4*)(wb + k * HIDC);
            a0 = fmaf(xv, w.x, a0);
            a1 = fmaf(xv, w.y, a1);
            a2 = fmaf(xv, w.z, a2);
            a3 = fmaf(xv, w.w, a3);
        }
    }
    long long node = base + local;
    if (node < NN)
        *(float4*)&g_h1[node * HIDC + cg] = make_float4(a0, a1, a2, a3);
}

// ---------------- layer-1 aggregate (gather) + self-loop + bias + relu + W2 dot ----------------
// 4 threads per node, 4 channels per thread.
__global__ void __launch_bounds__(256) agg1_fused_kernel(const float* __restrict__ b1,
                                                         const float* __restrict__ W2) {
    long long idx = (long long)blockIdx.x * blockDim.x + threadIdx.x;
    long long node = idx >> 2;
    if (node >= NN) return;
    int cg = (int)(idx & 3) * 4;

    int beg = g_start[node];
    int end = g_start[node + 1];
    float a0 = 0.f, a1 = 0.f, a2 = 0.f, a3 = 0.f;
    for (int e = beg; e < end; e++) {
        int2 cn = __ldg(&g_csr[e]);
        float norm = __int_as_float(cn.y);
        float4 h = *(const float4*)&g_h1[(long long)cn.x * HIDC + cg];
        a0 = fmaf(h.x, norm, a0);
        a1 = fmaf(h.y, norm, a1);
        a2 = fmaf(h.z, norm, a2);
        a3 = fmaf(h.w, norm, a3);
    }
    float di = g_dinv[node];
    float dii = di * di;
    float4 hs = *(const float4*)&g_h1[node * HIDC + cg];
    float4 bb = *(const float4*)&b1[cg];
    float4 w2 = *(const float4*)&W2[cg];
    float v = fmaxf(fmaf(hs.x, dii, a0) + bb.x, 0.f) * w2.x
            + fmaxf(fmaf(hs.y, dii, a1) + bb.y, 0.f) * w2.y
            + fmaxf(fmaf(hs.z, dii, a2) + bb.z, 0.f) * w2.z
            + fmaxf(fmaf(hs.w, dii, a3) + bb.w, 0.f) * w2.w;
    v += __shfl_down_sync(0xffffffffu, v, 2, 4);
    v += __shfl_down_sync(0xffffffffu, v, 1, 4);
    if ((idx & 3) == 0) g_h2[node] = v;
}

// ---------------- layer-2 aggregate (gather) + self-loop + bias + sigmoid ----------------
__global__ void agg2_final_kernel(const float* __restrict__ b2, float* __restrict__ out) {
    int i = blockIdx.x * blockDim.x + threadIdx.x;
    if (i >= NN) return;
    int beg = g_start[i];
    int end = g_start[i + 1];
    float acc = 0.f;
    for (int e = beg; e < end; e++) {
        int2 cn = __ldg(&g_csr[e]);
        acc = fmaf(g_h2[cn.x], __int_as_float(cn.y), acc);
    }
    float di = g_dinv[i];
    float v = acc + g_h2[i] * di * di + b2[0];
    out[i] = 1.0f / (1.0f + expf(-v));
}

extern "C" void kernel_launch(void* const* d_in, const int* in_sizes, int n_in,
                              void* d_out, int out_size) {
    const float* x  = (const float*)d_in[0];
    const void*  ei = d_in[1];
    const float* W1 = (const float*)d_in[2];
    const float* b1 = (const float*)d_in[3];
    const float* W2 = (const float*)d_in[4];
    const float* b2 = (const float*)d_in[5];
    float* out = (float*)d_out;

    void* p_degi;
    cudaGetSymbolAddress(&p_degi, g_degi);
    cudaMemsetAsync(p_degi, 0, (size_t)NN * sizeof(int));

    detect_kernel<<<1, 256>>>(ei);
    degree_pack_kernel<<<(EE + 255) / 256, 256>>>(ei);
    dinv_kernel<<<(NN + 255) / 256, 256>>>();

    scan1_kernel<<<NBLK, SCAN_B>>>();
    scan2_kernel<<<1, 128>>>();
    scan3_kernel<<<(NN + 255) / 256, 256>>>();

    scatter_kernel<<<(EE + 255) / 256, 256>>>();

    gemm1_kernel<<<(NN + 63) / 64, 256>>>(x, W1);

    long long t1 = (long long)NN * 4;
    agg1_fused_kernel<<<(unsigned)((t1 + 255) / 256), 256>>>(b1, W2);

    agg2_final_kernel<<<(NN + 255) / 256, 256>>>(b2, out);
}

// round 5
// speedup vs baseline: 1.7428x; 1.1119x over previous
#include <cuda_runtime.h>
#include <math.h>

#define NN   100000
#define EE   3200000
#define INC  128
#define HIDC 16
#define SCAN_B 1024
#define NBLK ((NN + SCAN_B - 1) / SCAN_B)   // 98

// ---------------- scratch ----------------
__device__ int   g_degi[NN];
__device__ float g_dinv[NN];
__device__ int2  g_sd[EE];
__device__ int   g_start[NN + 1];
__device__ int   g_cur[NN];
__device__ int   g_bsum[128];
__device__ int   g_csr[EE];                  // src only (features pre-scaled)
__device__ float g_h1[(long long)NN * HIDC]; // h1 * dinv[node]
__device__ float g_h2[NN];                   // h2 * dinv[node]
__device__ int   g_is64;

// ---------------- edge dtype auto-detect ----------------
__global__ void detect_kernel(const void* ei) {
    __shared__ int bad;
    if (threadIdx.x == 0) bad = 0;
    __syncthreads();
    const long long* p = (const long long*)ei;
    long long v = p[threadIdx.x];
    if (v < 0 || v >= NN) bad = 1;
    __syncthreads();
    if (threadIdx.x == 0) g_is64 = bad ? 0 : 1;
}

// ---------------- degree + pack ----------------
__global__ void degree_pack_kernel(const void* ei) {
    long long e = (long long)blockIdx.x * blockDim.x + threadIdx.x;
    if (e >= EE) return;
    int s, d;
    if (g_is64) {
        const long long* p = (const long long*)ei;
        s = (int)p[e];
        d = (int)p[(long long)EE + e];
    } else {
        const int* p = (const int*)ei;
        s = p[e];
        d = p[(long long)EE + e];
    }
    g_sd[e] = make_int2(s, d);
    atomicAdd(&g_degi[d], 1);
}

__global__ void dinv_kernel() {
    int i = blockIdx.x * blockDim.x + threadIdx.x;
    if (i >= NN) return;
    g_dinv[i] = rsqrtf((float)g_degi[i] + 1.0f);
}

// ---------------- prefix scan ----------------
__global__ void scan1_kernel() {
    __shared__ int sh[SCAN_B];
    int t = threadIdx.x;
    int i = blockIdx.x * SCAN_B + t;
    int v = (i < NN) ? g_degi[i] : 0;
    sh[t] = v;
#pragma unroll
    for (int off = 1; off < SCAN_B; off <<= 1) {
        __syncthreads();
        int add = (t >= off) ? sh[t - off] : 0;
        __syncthreads();
        sh[t] += add;
    }
    __syncthreads();
    if (i < NN) g_start[i] = sh[t] - v;
    if (t == SCAN_B - 1) g_bsum[blockIdx.x] = sh[t];
}

__global__ void scan2_kernel() {
    __shared__ int sh[128];
    int t = threadIdx.x;
    int v = (t < NBLK) ? g_bsum[t] : 0;
    sh[t] = v;
#pragma unroll
    for (int off = 1; off < 128; off <<= 1) {
        __syncthreads();
        int add = (t >= off) ? sh[t - off] : 0;
        __syncthreads();
        sh[t] += add;
    }
    __syncthreads();
    if (t < NBLK) g_bsum[t] = sh[t] - v;
}

__global__ void scan3_kernel() {
    int i = blockIdx.x * blockDim.x + threadIdx.x;
    if (i >= NN) return;
    int s = g_start[i] + g_bsum[i >> 10];
    g_start[i] = s;
    g_cur[i] = s;
    if (i == 0) g_start[NN] = EE;
}

// ---------------- scatter: CSR of src only ----------------
__global__ void scatter_kernel() {
    long long e = (long long)blockIdx.x * blockDim.x + threadIdx.x;
    if (e >= EE) return;
    int2 sd = g_sd[e];
    int pos = atomicAdd(&g_cur[sd.y], 1);
    g_csr[pos] = sd.x;
}

// ---------------- h1 = (x @ W1) * dinv[node] ----------------
__global__ void __launch_bounds__(256) gemm1_kernel(const float* __restrict__ x,
                                                    const float* __restrict__ W1) {
    __shared__ float sW[INC * HIDC];
    __shared__ float sx[64 * 68];
    int t = threadIdx.x;
    long long base = (long long)blockIdx.x * 64;
    int local = t >> 2;
    int cg    = (t & 3) * 4;

    for (int i = t; i < INC * HIDC; i += 256) sW[i] = W1[i];

    float a0 = 0.f, a1 = 0.f, a2 = 0.f, a3 = 0.f;

#pragma unroll
    for (int kt = 0; kt < 2; kt++) {
        __syncthreads();
        const float4* x4 = (const float4*)x;
        for (int j = t; j < 1024; j += 256) {
            int r = j >> 4, c4 = j & 15;
            long long node = base + r;
            float4 v = (node < NN) ? x4[node * 32 + kt * 16 + c4]
                                   : make_float4(0.f, 0.f, 0.f, 0.f);
            *(float4*)&sx[r * 68 + c4 * 4] = v;
        }
        __syncthreads();
        const float* xr = &sx[local * 68];
        const float* wb = &sW[kt * 64 * HIDC + cg];
#pragma unroll 8
        for (int k = 0; k < 64; k++) {
            float xv = xr[k];
            float4 w = *(const float4*)(wb + k * HIDC);
            a0 = fmaf(xv, w.x, a0);
            a1 = fmaf(xv, w.y, a1);
            a2 = fmaf(xv, w.z, a2);
            a3 = fmaf(xv, w.w, a3);
        }
    }
    long long node = base + local;
    if (node < NN) {
        float di = g_dinv[node];
        *(float4*)&g_h1[node * HIDC + cg] =
            make_float4(a0 * di, a1 * di, a2 * di, a3 * di);
    }
}

// ---------------- layer-1 gather + self-loop + bias + relu + W2 dot ----------------
// 4 threads/node, 4 channels each; edge loop unrolled x4 for MLP.
__global__ void __launch_bounds__(256) agg1_fused_kernel(const float* __restrict__ b1,
                                                         const float* __restrict__ W2) {
    long long idx = (long long)blockIdx.x * blockDim.x + threadIdx.x;
    long long node = idx >> 2;
    if (node >= NN) return;
    int cg = (int)(idx & 3) * 4;

    int beg = g_start[node];
    int end = g_start[node + 1];
    float a0 = 0.f, a1 = 0.f, a2 = 0.f, a3 = 0.f;
    int e = beg;
    for (; e + 4 <= end; e += 4) {
        int s0 = __ldg(&g_csr[e]);
        int s1 = __ldg(&g_csr[e + 1]);
        int s2 = __ldg(&g_csr[e + 2]);
        int s3 = __ldg(&g_csr[e + 3]);
        float4 h0 = *(const float4*)&g_h1[(long long)s0 * HIDC + cg];
        float4 h1 = *(const float4*)&g_h1[(long long)s1 * HIDC + cg];
        float4 h2 = *(const float4*)&g_h1[(long long)s2 * HIDC + cg];
        float4 h3 = *(const float4*)&g_h1[(long long)s3 * HIDC + cg];
        a0 += h0.x + h1.x + h2.x + h3.x;
        a1 += h0.y + h1.y + h2.y + h3.y;
        a2 += h0.z + h1.z + h2.z + h3.z;
        a3 += h0.w + h1.w + h2.w + h3.w;
    }
    for (; e < end; e++) {
        int s = __ldg(&g_csr[e]);
        float4 h = *(const float4*)&g_h1[(long long)s * HIDC + cg];
        a0 += h.x; a1 += h.y; a2 += h.z; a3 += h.w;
    }
    // self-loop: + h1_scaled[node]; then scale whole sum by dinv[node] (dst factor)
    float4 hs = *(const float4*)&g_h1[node * HIDC + cg];
    float di = g_dinv[node];
    float4 bb = *(const float4*)&b1[cg];
    float4 w2 = *(const float4*)&W2[cg];
    float v = fmaxf(fmaf(a0 + hs.x, di, bb.x), 0.f) * w2.x
            + fmaxf(fmaf(a1 + hs.y, di, bb.y), 0.f) * w2.y
            + fmaxf(fmaf(a2 + hs.z, di, bb.z), 0.f) * w2.z
            + fmaxf(fmaf(a3 + hs.w, di, bb.w), 0.f) * w2.w;
    v += __shfl_down_sync(0xffffffffu, v, 2, 4);
    v += __shfl_down_sync(0xffffffffu, v, 1, 4);
    if ((idx & 3) == 0) g_h2[node] = v * di;   // pre-scale for layer 2
}

// ---------------- layer-2 gather + self-loop + bias + sigmoid ----------------
// 4 threads/node, interleaved edges, shfl reduce.
__global__ void __launch_bounds__(256) agg2_final_kernel(const float* __restrict__ b2,
                                                         float* __restrict__ out) {
    long long idx = (long long)blockIdx.x * blockDim.x + threadIdx.x;
    long long node = idx >> 2;
    if (node >= NN) return;
    int l4 = (int)(idx & 3);

    int beg = g_start[node];
    int end = g_start[node + 1];
    float acc = 0.f;
    for (int e = beg + l4; e < end; e += 4)
        acc += g_h2[__ldg(&g_csr[e])];
    acc += __shfl_down_sync(0xffffffffu, acc, 2, 4);
    acc += __shfl_down_sync(0xffffffffu, acc, 1, 4);
    if (l4 == 0) {
        float di = g_dinv[node];
        float v = (acc + g_h2[node]) * di + b2[0];
        out[node] = 1.0f / (1.0f + expf(-v));
    }
}

extern "C" void kernel_launch(void* const* d_in, const int* in_sizes, int n_in,
                              void* d_out, int out_size) {
    const float* x  = (const float*)d_in[0];
    const void*  ei = d_in[1];
    const float* W1 = (const float*)d_in[2];
    const float* b1 = (const float*)d_in[3];
    const float* W2 = (const float*)d_in[4];
    const float* b2 = (const float*)d_in[5];
    float* out = (float*)d_out;

    void* p_degi;
    cudaGetSymbolAddress(&p_degi, g_degi);
    cudaMemsetAsync(p_degi, 0, (size_t)NN * sizeof(int));

    detect_kernel<<<1, 256>>>(ei);
    degree_pack_kernel<<<(EE + 255) / 256, 256>>>(ei);
    dinv_kernel<<<(NN + 255) / 256, 256>>>();

    scan1_kernel<<<NBLK, SCAN_B>>>();
    scan2_kernel<<<1, 128>>>();
    scan3_kernel<<<(NN + 255) / 256, 256>>>();

    scatter_kernel<<<(EE + 255) / 256, 256>>>();

    gemm1_kernel<<<(NN + 63) / 64, 256>>>(x, W1);

    long long t1 = (long long)NN * 4;
    agg1_fused_kernel<<<(unsigned)((t1 + 255) / 256), 256>>>(b1, W2);

    long long t2 = (long long)NN * 4;
    agg2_final_kernel<<<(unsigned)((t2 + 255) / 256), 256>>>(b2, out);
}